// round 1
// baseline (speedup 1.0000x reference)
#include <cuda_runtime.h>
#include <math.h>

// Problem dims (fixed for this problem instance)
#define BSZ 2048      // B*S
#define E   768
#define KN  36
#define H   4
#define HE  3072      // H*E

// ---------------- scratch (device globals; no allocation allowed) ----------------
__device__ __align__(16) float g_u[H * E];       // gamma .* (W1[h] @ W2y[h])
__device__ __align__(16) float g_v[H * E];       // gamma .* (W1[h] @ W2x[h])
__device__ __align__(16) float g_b1p[H * E];     // b1[h] + beta[h] @ W1[h]
__device__ float g_sumu[H];
__device__ float g_sumv[H];
__device__ float g_C[H];                          // b1p·(W2x+W2y) + b2
__device__ float g_logitx[BSZ * H];
__device__ __align__(16) float g_z[(size_t)BSZ * HE];    // per (n,h): gamma .* (sum_k w*y - s)
__device__ __align__(16) float g_cat[(size_t)BSZ * HE];  // gelu(x + a)

// ---------------- helpers ----------------
__device__ __forceinline__ float warp_sum(float v) {
#pragma unroll
    for (int o = 16; o > 0; o >>= 1) v += __shfl_xor_sync(0xffffffffu, v, o);
    return v;
}
__device__ __forceinline__ float warp_max(float v) {
#pragma unroll
    for (int o = 16; o > 0; o >>= 1) v = fmaxf(v, __shfl_xor_sync(0xffffffffu, v, o));
    return v;
}
// jax.nn.gelu default: tanh approximation
__device__ __forceinline__ float gelu_tanh(float x) {
    float x3 = x * x * x;
    float t = tanhf(0.7978845608028654f * (x + 0.044715f * x3));
    return 0.5f * x * (1.0f + t);
}

// ---------------- P1: u,v row dots ----------------
__global__ void k_p1(const float* __restrict__ W1, const float* __restrict__ W2x,
                     const float* __restrict__ W2y, const float* __restrict__ gamma) {
    int row = blockIdx.x * 8 + (threadIdx.x >> 5);   // row = h*E + e
    int lane = threadIdx.x & 31;
    if (row >= H * E) return;
    int h = row / E;
    const float* w  = W1 + (size_t)row * E;
    const float* wx = W2x + h * E;
    const float* wy = W2y + h * E;
    float dx = 0.f, dy = 0.f;
    for (int f = lane; f < E; f += 32) {
        float ww = w[f];
        dx += ww * wx[f];
        dy += ww * wy[f];
    }
    dx = warp_sum(dx); dy = warp_sum(dy);
    if (lane == 0) {
        float g = gamma[row];
        g_v[row] = g * dx;
        g_u[row] = g * dy;
    }
}

// ---------------- P2: b1' = b1 + beta @ W1 ----------------
__global__ void k_p2(const float* __restrict__ W1, const float* __restrict__ beta,
                     const float* __restrict__ b1) {
    int idx = blockIdx.x * blockDim.x + threadIdx.x;  // h*E + f
    if (idx >= H * E) return;
    int h = idx / E;
    int f = idx - h * E;
    const float* w  = W1 + (size_t)h * E * E + f;
    const float* bt = beta + h * E;
    float s = 0.f;
    for (int e = 0; e < E; e++) s += bt[e] * w[(size_t)e * E];
    g_b1p[idx] = b1[idx] + s;
}

// ---------------- P3: sums + constant term ----------------
__global__ void k_p3(const float* __restrict__ W2x, const float* __restrict__ W2y,
                     const float* __restrict__ b2) {
    int h = threadIdx.x >> 5;
    int lane = threadIdx.x & 31;
    float su = 0.f, sv = 0.f, c = 0.f;
    for (int e = lane; e < E; e += 32) {
        su += g_u[h * E + e];
        sv += g_v[h * E + e];
        c  += g_b1p[h * E + e] * (W2x[h * E + e] + W2y[h * E + e]);
    }
    su = warp_sum(su); sv = warp_sum(sv); c = warp_sum(c);
    if (lane == 0) {
        g_sumu[h] = su;
        g_sumv[h] = sv;
        g_C[h]    = c + b2[h];
    }
}

// ---------------- X: per-row x stats + logit_x ----------------
__global__ void k_x(const float* __restrict__ x) {
    int n = blockIdx.x * 8 + (threadIdx.x >> 5);
    int lane = threadIdx.x & 31;
    const float4* xr = (const float4*)(x + (size_t)n * E);
    const float4* v0 = (const float4*)(g_v);
    const float4* v1 = (const float4*)(g_v + E);
    const float4* v2 = (const float4*)(g_v + 2 * E);
    const float4* v3 = (const float4*)(g_v + 3 * E);
    float s = 0.f, s2 = 0.f, d0 = 0.f, d1 = 0.f, d2 = 0.f, d3 = 0.f;
#pragma unroll
    for (int i = 0; i < 6; i++) {
        int c = lane + i * 32;
        float4 xv = xr[c];
        float4 a = v0[c], b = v1[c], cc = v2[c], dd = v3[c];
        s  += xv.x + xv.y + xv.z + xv.w;
        s2 += xv.x * xv.x + xv.y * xv.y + xv.z * xv.z + xv.w * xv.w;
        d0 += xv.x * a.x + xv.y * a.y + xv.z * a.z + xv.w * a.w;
        d1 += xv.x * b.x + xv.y * b.y + xv.z * b.z + xv.w * b.w;
        d2 += xv.x * cc.x + xv.y * cc.y + xv.z * cc.z + xv.w * cc.w;
        d3 += xv.x * dd.x + xv.y * dd.y + xv.z * dd.z + xv.w * dd.w;
    }
    s = warp_sum(s); s2 = warp_sum(s2);
    d0 = warp_sum(d0); d1 = warp_sum(d1); d2 = warp_sum(d2); d3 = warp_sum(d3);
    if (lane == 0) {
        float mu = s * (1.0f / E);
        float rstd = rsqrtf(s2 * (1.0f / E) - mu * mu + 1e-5f);
        g_logitx[n * 4 + 0] = rstd * (d0 - mu * g_sumv[0]);
        g_logitx[n * 4 + 1] = rstd * (d1 - mu * g_sumv[1]);
        g_logitx[n * 4 + 2] = rstd * (d2 - mu * g_sumv[2]);
        g_logitx[n * 4 + 3] = rstd * (d3 - mu * g_sumv[3]);
    }
}

// ---------------- Y: per-n fused stats + logits + softmax + weighted sum ----------------
__global__ void k_y(const float* __restrict__ y, const float* __restrict__ gamma) {
    __shared__ float s_mu[KN];
    __shared__ float s_rstd[KN];
    __shared__ __align__(16) float s_lw[KN][4];  // logits, then w = prob*rstd
    __shared__ float s_sh[H];                    // s_h = sum_k w*mu
    int n = blockIdx.x;
    int wid = threadIdx.x >> 5;
    int lane = threadIdx.x & 31;

    const float4* u0 = (const float4*)(g_u);
    const float4* u1 = (const float4*)(g_u + E);
    const float4* u2 = (const float4*)(g_u + 2 * E);
    const float4* u3 = (const float4*)(g_u + 3 * E);

    // Phase 1: per-row stats + u-dots
    for (int k = wid; k < KN; k += 8) {
        const float4* yr = (const float4*)(y + ((size_t)n * KN + k) * E);
        float s = 0.f, s2 = 0.f, d0 = 0.f, d1 = 0.f, d2 = 0.f, d3 = 0.f;
#pragma unroll
        for (int i = 0; i < 6; i++) {
            int c = lane + i * 32;
            float4 yv = yr[c];
            float4 a = u0[c], b = u1[c], cc = u2[c], dd = u3[c];
            s  += yv.x + yv.y + yv.z + yv.w;
            s2 += yv.x * yv.x + yv.y * yv.y + yv.z * yv.z + yv.w * yv.w;
            d0 += yv.x * a.x + yv.y * a.y + yv.z * a.z + yv.w * a.w;
            d1 += yv.x * b.x + yv.y * b.y + yv.z * b.z + yv.w * b.w;
            d2 += yv.x * cc.x + yv.y * cc.y + yv.z * cc.z + yv.w * cc.w;
            d3 += yv.x * dd.x + yv.y * dd.y + yv.z * dd.z + yv.w * dd.w;
        }
        s = warp_sum(s); s2 = warp_sum(s2);
        d0 = warp_sum(d0); d1 = warp_sum(d1); d2 = warp_sum(d2); d3 = warp_sum(d3);
        if (lane == 0) {
            float mu = s * (1.0f / E);
            float rstd = rsqrtf(s2 * (1.0f / E) - mu * mu + 1e-5f);
            s_mu[k] = mu;
            s_rstd[k] = rstd;
            s_lw[k][0] = rstd * (d0 - mu * g_sumu[0]) + g_logitx[n * 4 + 0] + g_C[0];
            s_lw[k][1] = rstd * (d1 - mu * g_sumu[1]) + g_logitx[n * 4 + 1] + g_C[1];
            s_lw[k][2] = rstd * (d2 - mu * g_sumu[2]) + g_logitx[n * 4 + 2] + g_C[2];
            s_lw[k][3] = rstd * (d3 - mu * g_sumu[3]) + g_logitx[n * 4 + 3] + g_C[3];
        }
    }
    __syncthreads();

    // Phase 2: softmax over KN per head; w = prob*rstd; s_h = sum w*mu
    if (wid < 4) {
        int h = wid;
        int k1 = lane, k2 = lane + 32;
        float l1 = (k1 < KN) ? s_lw[k1][h] : -1e30f;
        float l2 = (k2 < KN) ? s_lw[k2][h] : -1e30f;
        float m = warp_max(fmaxf(l1, l2));
        float e1 = (k1 < KN) ? expf(l1 - m) : 0.f;
        float e2 = (k2 < KN) ? expf(l2 - m) : 0.f;
        float ss = warp_sum(e1 + e2);
        float inv = 1.0f / ss;
        float sh = 0.f;
        if (k1 < KN) {
            float w = e1 * inv * s_rstd[k1];
            s_lw[k1][h] = w;
            sh += w * s_mu[k1];
        }
        if (k2 < KN) {
            float w = e2 * inv * s_rstd[k2];
            s_lw[k2][h] = w;
            sh += w * s_mu[k2];
        }
        sh = warp_sum(sh);
        if (lane == 0) s_sh[h] = sh;
    }
    __syncthreads();

    // Phase 3: z[h,e] = gamma[h,e] * (sum_k w[k,h]*y[n,k,e] - s_h)
    int t = threadIdx.x;
    float acc[3][4];
#pragma unroll
    for (int c = 0; c < 3; c++)
#pragma unroll
        for (int h = 0; h < 4; h++) acc[c][h] = 0.f;
    const float* yb = y + (size_t)n * KN * E;
#pragma unroll 4
    for (int k = 0; k < KN; k++) {
        float4 w = *(const float4*)(&s_lw[k][0]);
        float y0 = yb[k * E + t];
        float y1 = yb[k * E + t + 256];
        float y2 = yb[k * E + t + 512];
        acc[0][0] += y0 * w.x; acc[0][1] += y0 * w.y; acc[0][2] += y0 * w.z; acc[0][3] += y0 * w.w;
        acc[1][0] += y1 * w.x; acc[1][1] += y1 * w.y; acc[1][2] += y1 * w.z; acc[1][3] += y1 * w.w;
        acc[2][0] += y2 * w.x; acc[2][1] += y2 * w.y; acc[2][2] += y2 * w.z; acc[2][3] += y2 * w.w;
    }
    float sh0 = s_sh[0], sh1 = s_sh[1], sh2 = s_sh[2], sh3 = s_sh[3];
#pragma unroll
    for (int c = 0; c < 3; c++) {
        int e = t + c * 256;
        size_t base = (size_t)n * HE;
        g_z[base + 0 * E + e] = gamma[0 * E + e] * (acc[c][0] - sh0);
        g_z[base + 1 * E + e] = gamma[1 * E + e] * (acc[c][1] - sh1);
        g_z[base + 2 * E + e] = gamma[2 * E + e] * (acc[c][2] - sh2);
        g_z[base + 3 * E + e] = gamma[3 * E + e] * (acc[c][3] - sh3);
    }
}

// ---------------- GEMM: BM=128, BN=64, BK=16, 256 threads, 8x4 micro ----------------
// MODE 0: C(g_cat)[n, h*E+f] = gelu(x[n,f] + A(g_z)@W1[h] + b1p[h,f]); grid.z = h
// MODE 1: C(out)[n,f]        = x[n,f] + gelu(A(g_cat)@Wm + bm[f])
template <int MODE>
__global__ void k_gemm(const float* __restrict__ Bg, const float* __restrict__ biasg,
                       const float* __restrict__ xres, float* __restrict__ Cout, int Kdim) {
    __shared__ float As[16][128];
    __shared__ float Bs[16][64];

    const float* A;
    const float* B;
    const float* bias;
    float* C;
    int lda, ldb, ldc;
    if (MODE == 0) {
        int h = blockIdx.z;
        A = g_z + h * E;    lda = HE;
        B = Bg + (size_t)h * E * E;  ldb = E;
        bias = g_b1p + h * E;
        C = g_cat + h * E;  ldc = HE;
    } else {
        A = g_cat;          lda = HE;
        B = Bg;             ldb = E;
        bias = biasg;
        C = Cout;           ldc = E;
    }

    int tid = threadIdx.x;
    int tx = tid & 15;   // 0..15 -> 4 cols each
    int ty = tid >> 4;   // 0..15 -> 8 rows each
    int m0 = blockIdx.y * 128;
    int n0 = blockIdx.x * 64;

    float acc[8][4];
#pragma unroll
    for (int i = 0; i < 8; i++)
#pragma unroll
        for (int j = 0; j < 4; j++) acc[i][j] = 0.f;

    for (int k0 = 0; k0 < Kdim; k0 += 16) {
        // A tile 128x16 -> As[k][m] (transposed store)
#pragma unroll
        for (int tq = 0; tq < 2; tq++) {
            int fid = tid * 2 + tq;      // 0..511
            int row = fid >> 2;
            int kq = fid & 3;
            float4 a = *(const float4*)(A + (size_t)(m0 + row) * lda + k0 + kq * 4);
            As[kq * 4 + 0][row] = a.x;
            As[kq * 4 + 1][row] = a.y;
            As[kq * 4 + 2][row] = a.z;
            As[kq * 4 + 3][row] = a.w;
        }
        // B tile 16x64
        {
            int row = tid >> 4;
            int c4 = tid & 15;
            float4 b = *(const float4*)(B + (size_t)(k0 + row) * ldb + n0 + c4 * 4);
            *(float4*)(&Bs[row][c4 * 4]) = b;
        }
        __syncthreads();
#pragma unroll
        for (int kk = 0; kk < 16; kk++) {
            float a[8], b[4];
            *(float4*)(a)     = *(const float4*)(&As[kk][ty * 8]);
            *(float4*)(a + 4) = *(const float4*)(&As[kk][ty * 8 + 4]);
            *(float4*)(b)     = *(const float4*)(&Bs[kk][tx * 4]);
#pragma unroll
            for (int i = 0; i < 8; i++)
#pragma unroll
                for (int j = 0; j < 4; j++) acc[i][j] = fmaf(a[i], b[j], acc[i][j]);
        }
        __syncthreads();
    }

    // epilogue
#pragma unroll
    for (int i = 0; i < 8; i++) {
        int m = m0 + ty * 8 + i;
#pragma unroll
        for (int j = 0; j < 4; j++) {
            int nn = n0 + tx * 4 + j;
            float v = acc[i][j] + bias[nn];
            float xr = xres[(size_t)m * E + nn];
            float o;
            if (MODE == 0) o = gelu_tanh(xr + v);
            else           o = xr + gelu_tanh(v);
            C[(size_t)m * ldc + nn] = o;
        }
    }
}

// ---------------- launch ----------------
extern "C" void kernel_launch(void* const* d_in, const int* in_sizes, int n_in,
                              void* d_out, int out_size) {
    const float* x     = (const float*)d_in[0];
    const float* y     = (const float*)d_in[1];
    const float* gamma = (const float*)d_in[2];
    const float* beta  = (const float*)d_in[3];
    const float* W1    = (const float*)d_in[4];
    const float* b1    = (const float*)d_in[5];
    const float* W2x   = (const float*)d_in[6];
    const float* W2y   = (const float*)d_in[7];
    const float* b2    = (const float*)d_in[8];
    const float* Wm    = (const float*)d_in[9];
    const float* bm    = (const float*)d_in[10];
    float* out = (float*)d_out;

    k_p1<<<H * E / 8, 256>>>(W1, W2x, W2y, gamma);
    k_p2<<<(H * E + 255) / 256, 256>>>(W1, beta, b1);
    k_p3<<<1, 128>>>(W2x, W2y, b2);
    k_x<<<BSZ / 8, 256>>>(x);
    k_y<<<BSZ, 256>>>(y, gamma);
    k_gemm<0><<<dim3(E / 64, BSZ / 128, H), 256>>>(W1, nullptr, x, nullptr, E);
    k_gemm<1><<<dim3(E / 64, BSZ / 128, 1), 256>>>(Wm, bm, x, out, HE);
}

// round 7
// speedup vs baseline: 1.5866x; 1.5866x over previous
#include <cuda_runtime.h>
#include <cuda_bf16.h>
#include <math.h>
#include <stdint.h>

// Problem dims (fixed for this problem instance)
#define BSZ 2048      // B*S
#define E   768
#define KN  36
#define H   4
#define HE  3072      // H*E

// ================= scratch (device globals; no allocation allowed) =================
__device__ __align__(16) float g_u[H * E];       // gamma .* (W1[h] @ W2y[h])
__device__ __align__(16) float g_v[H * E];       // gamma .* (W1[h] @ W2x[h])
__device__ __align__(16) float g_b1p[H * E];     // b1[h] + beta[h] @ W1[h]
__device__ float g_sumu[H];
__device__ float g_sumv[H];
__device__ float g_C[H];                          // b1p·(W2x+W2y) + b2
__device__ float g_logitx[BSZ * H];

// bf16 hi/lo split operands for HMMA GEMMs
__device__ __align__(16) __nv_bfloat16 g_z_hi[(size_t)BSZ * HE];
__device__ __align__(16) __nv_bfloat16 g_z_lo[(size_t)BSZ * HE];
__device__ __align__(16) __nv_bfloat16 g_cat_hi[(size_t)BSZ * HE];
__device__ __align__(16) __nv_bfloat16 g_cat_lo[(size_t)BSZ * HE];
__device__ __align__(16) __nv_bfloat16 g_w1t_hi[(size_t)H * E * E];  // [h][f][e] = W1[h][e][f]
__device__ __align__(16) __nv_bfloat16 g_w1t_lo[(size_t)H * E * E];
__device__ __align__(16) __nv_bfloat16 g_wmt_hi[(size_t)E * HE];     // [f][e2] = Wm[e2][f]
__device__ __align__(16) __nv_bfloat16 g_wmt_lo[(size_t)E * HE];

// ================= helpers =================
__device__ __forceinline__ float warp_sum(float v) {
#pragma unroll
    for (int o = 16; o > 0; o >>= 1) v += __shfl_xor_sync(0xffffffffu, v, o);
    return v;
}
__device__ __forceinline__ float warp_max(float v) {
#pragma unroll
    for (int o = 16; o > 0; o >>= 1) v = fmaxf(v, __shfl_xor_sync(0xffffffffu, v, o));
    return v;
}
// jax.nn.gelu default: tanh approximation (fast exp-based tanh, rel err ~1e-6)
__device__ __forceinline__ float gelu_tanh(float x) {
    float u = 0.7978845608028654f * x * (1.0f + 0.044715f * x * x);
    u = fminf(u, 12.0f);
    float e = __expf(2.0f * u);
    float t = __fdividef(e - 1.0f, e + 1.0f);
    return 0.5f * x * (1.0f + t);
}

// ---- mma.sync bf16 (sm_80-compatible; works at compute_103 virtual arch) ----
#define MMA_BF16(c, a, b) \
    asm volatile("mma.sync.aligned.m16n8k16.row.col.f32.bf16.bf16.f32 " \
                 "{%0,%1,%2,%3}, {%4,%5,%6,%7}, {%8,%9}, {%0,%1,%2,%3};" \
                 : "+f"((c)[0]), "+f"((c)[1]), "+f"((c)[2]), "+f"((c)[3]) \
                 : "r"((a)[0]), "r"((a)[1]), "r"((a)[2]), "r"((a)[3]), \
                   "r"((b)[0]), "r"((b)[1]))

__device__ __forceinline__ uint32_t smem_to_u32(const void* p) {
    uint32_t a;
    asm("{ .reg .u64 t; cvta.to.shared.u64 t, %1; cvt.u32.u64 %0, t; }" : "=r"(a) : "l"(p));
    return a;
}
__device__ __forceinline__ void cp_async16(uint32_t dst, const void* src) {
    asm volatile("cp.async.cg.shared.global [%0], [%1], 16;" :: "r"(dst), "l"(src) : "memory");
}
__device__ __forceinline__ void cp_commit() {
    asm volatile("cp.async.commit_group;" ::: "memory");
}

// ================= P1: u,v row dots =================
__global__ void k_p1(const float* __restrict__ W1, const float* __restrict__ W2x,
                     const float* __restrict__ W2y, const float* __restrict__ gamma) {
    int row = blockIdx.x * 8 + (threadIdx.x >> 5);   // row = h*E + e
    int lane = threadIdx.x & 31;
    if (row >= H * E) return;
    int h = row / E;
    const float* w  = W1 + (size_t)row * E;
    const float* wx = W2x + h * E;
    const float* wy = W2y + h * E;
    float dx = 0.f, dy = 0.f;
    for (int f = lane; f < E; f += 32) {
        float ww = w[f];
        dx += ww * wx[f];
        dy += ww * wy[f];
    }
    dx = warp_sum(dx); dy = warp_sum(dy);
    if (lane == 0) {
        float g = gamma[row];
        g_v[row] = g * dx;
        g_u[row] = g * dy;
    }
}

// ================= P2: b1' = b1 + beta @ W1 (coalesced) =================
__global__ void k_p2(const float* __restrict__ W1, const float* __restrict__ beta,
                     const float* __restrict__ b1) {
    int h = blockIdx.y;
    int f = blockIdx.x * 256 + threadIdx.x;
    const float* w  = W1 + (size_t)h * E * E + f;
    const float* bt = beta + h * E;
    float s = 0.f;
    for (int e = 0; e < E; e++) s += bt[e] * w[(size_t)e * E];
    g_b1p[h * E + f] = b1[h * E + f] + s;
}

// ================= P3: sums + constant term =================
__global__ void k_p3(const float* __restrict__ W2x, const float* __restrict__ W2y,
                     const float* __restrict__ b2) {
    int h = threadIdx.x >> 5;
    int lane = threadIdx.x & 31;
    float su = 0.f, sv = 0.f, c = 0.f;
    for (int e = lane; e < E; e += 32) {
        su += g_u[h * E + e];
        sv += g_v[h * E + e];
        c  += g_b1p[h * E + e] * (W2x[h * E + e] + W2y[h * E + e]);
    }
    su = warp_sum(su); sv = warp_sum(sv); c = warp_sum(c);
    if (lane == 0) {
        g_sumu[h] = su;
        g_sumv[h] = sv;
        g_C[h]    = c + b2[h];
    }
}

// ================= transpose + hi/lo split of weights =================
// W1[h][e][f] -> w1t[h][f][e]
__global__ void k_tw1(const float* __restrict__ W1) {
    __shared__ float t[32][33];
    int h = blockIdx.z;
    int f0 = blockIdx.x * 32, e0 = blockIdx.y * 32;
    const float* src = W1 + (size_t)h * E * E;
    int tx = threadIdx.x;
    for (int i = threadIdx.y; i < 32; i += 8)
        t[i][tx] = src[(size_t)(e0 + i) * E + f0 + tx];
    __syncthreads();
    for (int i = threadIdx.y; i < 32; i += 8) {
        float v = t[tx][i];   // = W1[h][e0+tx][f0+i]
        __nv_bfloat16 hb = __float2bfloat16(v);
        size_t o = ((size_t)h * E + f0 + i) * E + e0 + tx;
        g_w1t_hi[o] = hb;
        g_w1t_lo[o] = __float2bfloat16(v - __bfloat162float(hb));
    }
}
// Wm[e2][f] -> wmt[f][e2]
__global__ void k_twm(const float* __restrict__ Wm) {
    __shared__ float t[32][33];
    int f0 = blockIdx.x * 32, r0 = blockIdx.y * 32;
    int tx = threadIdx.x;
    for (int i = threadIdx.y; i < 32; i += 8)
        t[i][tx] = Wm[(size_t)(r0 + i) * E + f0 + tx];
    __syncthreads();
    for (int i = threadIdx.y; i < 32; i += 8) {
        float v = t[tx][i];   // = Wm[r0+tx][f0+i]
        __nv_bfloat16 hb = __float2bfloat16(v);
        size_t o = (size_t)(f0 + i) * HE + r0 + tx;
        g_wmt_hi[o] = hb;
        g_wmt_lo[o] = __float2bfloat16(v - __bfloat162float(hb));
    }
}

// ================= X: per-row x stats + logit_x =================
__global__ void k_x(const float* __restrict__ x) {
    int n = blockIdx.x * 8 + (threadIdx.x >> 5);
    int lane = threadIdx.x & 31;
    const float4* xr = (const float4*)(x + (size_t)n * E);
    const float4* v0 = (const float4*)(g_v);
    const float4* v1 = (const float4*)(g_v + E);
    const float4* v2 = (const float4*)(g_v + 2 * E);
    const float4* v3 = (const float4*)(g_v + 3 * E);
    float s = 0.f, s2 = 0.f, d0 = 0.f, d1 = 0.f, d2 = 0.f, d3 = 0.f;
#pragma unroll
    for (int i = 0; i < 6; i++) {
        int c = lane + i * 32;
        float4 xv = xr[c];
        float4 a = v0[c], b = v1[c], cc = v2[c], dd = v3[c];
        s  += xv.x + xv.y + xv.z + xv.w;
        s2 += xv.x * xv.x + xv.y * xv.y + xv.z * xv.z + xv.w * xv.w;
        d0 += xv.x * a.x + xv.y * a.y + xv.z * a.z + xv.w * a.w;
        d1 += xv.x * b.x + xv.y * b.y + xv.z * b.z + xv.w * b.w;
        d2 += xv.x * cc.x + xv.y * cc.y + xv.z * cc.z + xv.w * cc.w;
        d3 += xv.x * dd.x + xv.y * dd.y + xv.z * dd.z + xv.w * dd.w;
    }
    s = warp_sum(s); s2 = warp_sum(s2);
    d0 = warp_sum(d0); d1 = warp_sum(d1); d2 = warp_sum(d2); d3 = warp_sum(d3);
    if (lane == 0) {
        float mu = s * (1.0f / E);
        float rstd = rsqrtf(s2 * (1.0f / E) - mu * mu + 1e-5f);
        g_logitx[n * 4 + 0] = rstd * (d0 - mu * g_sumv[0]);
        g_logitx[n * 4 + 1] = rstd * (d1 - mu * g_sumv[1]);
        g_logitx[n * 4 + 2] = rstd * (d2 - mu * g_sumv[2]);
        g_logitx[n * 4 + 3] = rstd * (d3 - mu * g_sumv[3]);
    }
}

// ================= Y: fused stats + logits + softmax + weighted sum (smem-cached y) =================
extern __shared__ float s_y_dyn[];
__global__ void __launch_bounds__(256) k_y(const float* __restrict__ y,
                                           const float* __restrict__ gamma) {
    __shared__ float s_mu[KN];
    __shared__ float s_rstd[KN];
    __shared__ __align__(16) float s_lw[KN][4];  // logits, then w = prob*rstd
    __shared__ float s_sh[H];
    int n = blockIdx.x;
    int wid = threadIdx.x >> 5;
    int lane = threadIdx.x & 31;

    const float4* u0 = (const float4*)(g_u);
    const float4* u1 = (const float4*)(g_u + E);
    const float4* u2 = (const float4*)(g_u + 2 * E);
    const float4* u3 = (const float4*)(g_u + 3 * E);

    // Phase 1: per-row stats + u-dots, caching y rows in smem
    for (int k = wid; k < KN; k += 8) {
        const float4* yr = (const float4*)(y + ((size_t)n * KN + k) * E);
        float4* sr = (float4*)(s_y_dyn + k * E);
        float s = 0.f, s2 = 0.f, d0 = 0.f, d1 = 0.f, d2 = 0.f, d3 = 0.f;
#pragma unroll
        for (int i = 0; i < 6; i++) {
            int c = lane + i * 32;
            float4 yv = yr[c];
            sr[c] = yv;
            float4 a = u0[c], b = u1[c], cc = u2[c], dd = u3[c];
            s  += yv.x + yv.y + yv.z + yv.w;
            s2 += yv.x * yv.x + yv.y * yv.y + yv.z * yv.z + yv.w * yv.w;
            d0 += yv.x * a.x + yv.y * a.y + yv.z * a.z + yv.w * a.w;
            d1 += yv.x * b.x + yv.y * b.y + yv.z * b.z + yv.w * b.w;
            d2 += yv.x * cc.x + yv.y * cc.y + yv.z * cc.z + yv.w * cc.w;
            d3 += yv.x * dd.x + yv.y * dd.y + yv.z * dd.z + yv.w * dd.w;
        }
        s = warp_sum(s); s2 = warp_sum(s2);
        d0 = warp_sum(d0); d1 = warp_sum(d1); d2 = warp_sum(d2); d3 = warp_sum(d3);
        if (lane == 0) {
            float mu = s * (1.0f / E);
            float rstd = rsqrtf(s2 * (1.0f / E) - mu * mu + 1e-5f);
            s_mu[k] = mu;
            s_rstd[k] = rstd;
            s_lw[k][0] = rstd * (d0 - mu * g_sumu[0]) + g_logitx[n * 4 + 0] + g_C[0];
            s_lw[k][1] = rstd * (d1 - mu * g_sumu[1]) + g_logitx[n * 4 + 1] + g_C[1];
            s_lw[k][2] = rstd * (d2 - mu * g_sumu[2]) + g_logitx[n * 4 + 2] + g_C[2];
            s_lw[k][3] = rstd * (d3 - mu * g_sumu[3]) + g_logitx[n * 4 + 3] + g_C[3];
        }
    }
    __syncthreads();

    // Phase 2: softmax over KN per head; w = prob*rstd; s_h = sum w*mu
    if (wid < 4) {
        int h = wid;
        int k1 = lane, k2 = lane + 32;
        float l1 = (k1 < KN) ? s_lw[k1][h] : -1e30f;
        float l2 = (k2 < KN) ? s_lw[k2][h] : -1e30f;
        float m = warp_max(fmaxf(l1, l2));
        float e1 = (k1 < KN) ? expf(l1 - m) : 0.f;
        float e2 = (k2 < KN) ? expf(l2 - m) : 0.f;
        float ss = warp_sum(e1 + e2);
        float inv = 1.0f / ss;
        float sh = 0.f;
        if (k1 < KN) {
            float w = e1 * inv * s_rstd[k1];
            s_lw[k1][h] = w;
            sh += w * s_mu[k1];
        }
        if (k2 < KN) {
            float w = e2 * inv * s_rstd[k2];
            s_lw[k2][h] = w;
            sh += w * s_mu[k2];
        }
        sh = warp_sum(sh);
        if (lane == 0) s_sh[h] = sh;
    }
    __syncthreads();

    // Phase 3: z[h,e] = gamma[h,e] * (sum_k w[k,h]*y[n,k,e] - s_h); write bf16 hi/lo
    int t = threadIdx.x;
    float acc[3][4];
#pragma unroll
    for (int c = 0; c < 3; c++)
#pragma unroll
        for (int h = 0; h < 4; h++) acc[c][h] = 0.f;
#pragma unroll 4
    for (int k = 0; k < KN; k++) {
        float4 w = *(const float4*)(&s_lw[k][0]);
        float y0 = s_y_dyn[k * E + t];
        float y1 = s_y_dyn[k * E + t + 256];
        float y2 = s_y_dyn[k * E + t + 512];
        acc[0][0] += y0 * w.x; acc[0][1] += y0 * w.y; acc[0][2] += y0 * w.z; acc[0][3] += y0 * w.w;
        acc[1][0] += y1 * w.x; acc[1][1] += y1 * w.y; acc[1][2] += y1 * w.z; acc[1][3] += y1 * w.w;
        acc[2][0] += y2 * w.x; acc[2][1] += y2 * w.y; acc[2][2] += y2 * w.z; acc[2][3] += y2 * w.w;
    }
    float sh0 = s_sh[0], sh1 = s_sh[1], sh2 = s_sh[2], sh3 = s_sh[3];
#pragma unroll
    for (int c = 0; c < 3; c++) {
        int e = t + c * 256;
        size_t base = (size_t)n * HE;
        float vals[4] = { acc[c][0] - sh0, acc[c][1] - sh1, acc[c][2] - sh2, acc[c][3] - sh3 };
#pragma unroll
        for (int hh = 0; hh < 4; hh++) {
            float v = gamma[hh * E + e] * vals[hh];
            __nv_bfloat16 hb = __float2bfloat16(v);
            g_z_hi[base + hh * E + e] = hb;
            g_z_lo[base + hh * E + e] = __float2bfloat16(v - __bfloat162float(hb));
        }
    }
}

// ================= HMMA GEMM (mma.sync bf16, hi/lo split, fp32 accum) =================
// Block tile 128x128, BK=32, 256 threads (8 warps, 2x4), warp tile 64x32.
// MODE 0: cat[n, h*E+f] = gelu(x[n,f] + z[n,h]@W1[h] + b1p[h,f])  (grid.z = h), write bf16 hi/lo
// MODE 1: out[n,f]      = x[n,f] + gelu(cat@Wm + bm[f])
#define PAD    40          // smem row stride in bf16 elems (80B = 20 banks; conflict-free)
#define MATSZ  (128 * PAD * 2)            // 10240 B per matrix tile
#define STAGE  (4 * MATSZ)                // Ah, Al, Bh, Bl
#define SMEM_MMA (2 * STAGE)              // double buffered: 81920 B

extern __shared__ __align__(128) char s_mma_dyn[];

__device__ __forceinline__ void cp_tile(const __nv_bfloat16* __restrict__ src, int ld,
                                        uint32_t dst, int tid) {
#pragma unroll
    for (int q = 0; q < 2; q++) {
        int cid = q * 256 + tid;        // 0..511 (128 rows x 4 16B-chunks)
        int row = cid >> 2;
        int c   = cid & 3;
        cp_async16(dst + row * (PAD * 2) + c * 16, src + (size_t)row * ld + c * 8);
    }
}

template <int MODE>
__global__ void __launch_bounds__(256)
k_mma(const float* __restrict__ xres, const float* __restrict__ bm_in,
      float* __restrict__ outp) {
    const int tid = threadIdx.x, wid = tid >> 5, lane = tid & 31;
    const int g = lane >> 2, tig = lane & 3;
    const int wm = wid >> 2, wn = wid & 3;       // 2 x 4 warp grid
    const int m0 = blockIdx.y * 128, n0 = blockIdx.x * 128;
    constexpr int Kdim = (MODE == 0) ? E : HE;
    constexpr int NCH = Kdim / 32;

    const __nv_bfloat16 *Ah, *Al, *Bh, *Bl;
    const float* bias;
    int lda, ldb, hh;
    if (MODE == 0) {
        hh = blockIdx.z;
        Ah = g_z_hi + hh * E;  Al = g_z_lo + hh * E;  lda = HE;
        Bh = g_w1t_hi + (size_t)hh * E * E;  Bl = g_w1t_lo + (size_t)hh * E * E;  ldb = E;
        bias = g_b1p + hh * E;
    } else {
        hh = 0;
        Ah = g_cat_hi;  Al = g_cat_lo;  lda = HE;
        Bh = g_wmt_hi;  Bl = g_wmt_lo;  ldb = HE;
        bias = bm_in;
    }
    Ah += (size_t)m0 * lda;  Al += (size_t)m0 * lda;
    Bh += (size_t)n0 * ldb;  Bl += (size_t)n0 * ldb;

    uint32_t sbase = smem_to_u32(s_mma_dyn);

    float acc[4][4][4];
#pragma unroll
    for (int i = 0; i < 4; i++)
#pragma unroll
        for (int j = 0; j < 4; j++)
#pragma unroll
            for (int r = 0; r < 4; r++) acc[i][j][r] = 0.f;

    // prefetch chunks 0 and 1
#pragma unroll
    for (int pf = 0; pf < 2; pf++) {
        uint32_t sb = sbase + pf * STAGE;
        cp_tile(Ah + pf * 32, lda, sb,             tid);
        cp_tile(Al + pf * 32, lda, sb + MATSZ,     tid);
        cp_tile(Bh + pf * 32, ldb, sb + 2 * MATSZ, tid);
        cp_tile(Bl + pf * 32, ldb, sb + 3 * MATSZ, tid);
        cp_commit();
    }

    for (int kc = 0; kc < NCH; kc++) {
        if (kc < NCH - 1) asm volatile("cp.async.wait_group 1;" ::: "memory");
        else              asm volatile("cp.async.wait_group 0;" ::: "memory");
        __syncthreads();

        const char* sb = s_mma_dyn + (kc & 1) * STAGE;
        const __nv_bfloat16* sAh = (const __nv_bfloat16*)(sb);
        const __nv_bfloat16* sAl = (const __nv_bfloat16*)(sb + MATSZ);
        const __nv_bfloat16* sBh = (const __nv_bfloat16*)(sb + 2 * MATSZ);
        const __nv_bfloat16* sBl = (const __nv_bfloat16*)(sb + 3 * MATSZ);

#pragma unroll
        for (int ks = 0; ks < 2; ks++) {
            const int k0 = ks * 16;
            uint32_t bh[4][2], bl[4][2];
#pragma unroll
            for (int ni = 0; ni < 4; ni++) {
                int nrow = wn * 32 + ni * 8 + g;
                bh[ni][0] = *(const uint32_t*)(sBh + nrow * PAD + k0 + 2 * tig);
                bh[ni][1] = *(const uint32_t*)(sBh + nrow * PAD + k0 + 8 + 2 * tig);
                bl[ni][0] = *(const uint32_t*)(sBl + nrow * PAD + k0 + 2 * tig);
                bl[ni][1] = *(const uint32_t*)(sBl + nrow * PAD + k0 + 8 + 2 * tig);
            }
#pragma unroll
            for (int mi = 0; mi < 4; mi++) {
                int mrow = wm * 64 + mi * 16 + g;
                uint32_t ah[4], al[4];
                ah[0] = *(const uint32_t*)(sAh + mrow * PAD + k0 + 2 * tig);
                ah[1] = *(const uint32_t*)(sAh + (mrow + 8) * PAD + k0 + 2 * tig);
                ah[2] = *(const uint32_t*)(sAh + mrow * PAD + k0 + 8 + 2 * tig);
                ah[3] = *(const uint32_t*)(sAh + (mrow + 8) * PAD + k0 + 8 + 2 * tig);
                al[0] = *(const uint32_t*)(sAl + mrow * PAD + k0 + 2 * tig);
                al[1] = *(const uint32_t*)(sAl + (mrow + 8) * PAD + k0 + 2 * tig);
                al[2] = *(const uint32_t*)(sAl + mrow * PAD + k0 + 8 + 2 * tig);
                al[3] = *(const uint32_t*)(sAl + (mrow + 8) * PAD + k0 + 8 + 2 * tig);
#pragma unroll
                for (int ni = 0; ni < 4; ni++) {
                    MMA_BF16(acc[mi][ni], ah, bh[ni]);
                    MMA_BF16(acc[mi][ni], ah, bl[ni]);
                    MMA_BF16(acc[mi][ni], al, bh[ni]);
                }
            }
        }
        __syncthreads();

        if (kc + 2 < NCH) {
            uint32_t sb2 = sbase + (kc & 1) * STAGE;
            int ko = (kc + 2) * 32;
            cp_tile(Ah + ko, lda, sb2,             tid);
            cp_tile(Al + ko, lda, sb2 + MATSZ,     tid);
            cp_tile(Bh + ko, ldb, sb2 + 2 * MATSZ, tid);
            cp_tile(Bl + ko, ldb, sb2 + 3 * MATSZ, tid);
            cp_commit();
        }
    }

    // ---- epilogue ----
#pragma unroll
    for (int mi = 0; mi < 4; mi++) {
#pragma unroll
        for (int ni = 0; ni < 4; ni++) {
            int n = n0 + wn * 32 + ni * 8 + 2 * tig;          // within [0,E) column space
#pragma unroll
            for (int half = 0; half < 2; half++) {
                int m = m0 + wm * 64 + mi * 16 + g + half * 8;
                float v0 = acc[mi][ni][half * 2 + 0];
                float v1 = acc[mi][ni][half * 2 + 1];
                float2 xv = *(const float2*)(xres + (size_t)m * E + n);
                float2 bv = *(const float2*)(bias + n);
                if (MODE == 0) {
                    float o0 = gelu_tanh(xv.x + v0 + bv.x);
                    float o1 = gelu_tanh(xv.y + v1 + bv.y);
                    __nv_bfloat16 h0 = __float2bfloat16(o0), h1 = __float2bfloat16(o1);
                    __nv_bfloat16 L0 = __float2bfloat16(o0 - __bfloat162float(h0));
                    __nv_bfloat16 L1 = __float2bfloat16(o1 - __bfloat162float(h1));
                    size_t oidx = (size_t)m * HE + hh * E + n;
                    *(uint32_t*)(g_cat_hi + oidx) =
                        ((uint32_t)__bfloat16_as_ushort(h1) << 16) | __bfloat16_as_ushort(h0);
                    *(uint32_t*)(g_cat_lo + oidx) =
                        ((uint32_t)__bfloat16_as_ushort(L1) << 16) | __bfloat16_as_ushort(L0);
                } else {
                    float2 o;
                    o.x = xv.x + gelu_tanh(v0 + bv.x);
                    o.y = xv.y + gelu_tanh(v1 + bv.y);
                    *(float2*)(outp + (size_t)m * E + n) = o;
                }
            }
        }
    }
}

// ================= launch =================
extern "C" void kernel_launch(void* const* d_in, const int* in_sizes, int n_in,
                              void* d_out, int out_size) {
    const float* x     = (const float*)d_in[0];
    const float* y     = (const float*)d_in[1];
    const float* gamma = (const float*)d_in[2];
    const float* beta  = (const float*)d_in[3];
    const float* W1    = (const float*)d_in[4];
    const float* b1    = (const float*)d_in[5];
    const float* W2x   = (const float*)d_in[6];
    const float* W2y   = (const float*)d_in[7];
    const float* b2    = (const float*)d_in[8];
    const float* Wm    = (const float*)d_in[9];
    const float* bm    = (const float*)d_in[10];
    float* out = (float*)d_out;

    const int SMEM_Y = KN * E * sizeof(float);   // 110592
    cudaFuncSetAttribute(k_y, cudaFuncAttributeMaxDynamicSharedMemorySize, SMEM_Y);
    cudaFuncSetAttribute(k_mma<0>, cudaFuncAttributeMaxDynamicSharedMemorySize, SMEM_MMA);
    cudaFuncSetAttribute(k_mma<1>, cudaFuncAttributeMaxDynamicSharedMemorySize, SMEM_MMA);

    k_p1<<<H * E / 8, 256>>>(W1, W2x, W2y, gamma);
    k_p2<<<dim3(E / 256, H), 256>>>(W1, beta, b1);
    k_p3<<<1, 128>>>(W2x, W2y, b2);
    k_tw1<<<dim3(E / 32, E / 32, H), dim3(32, 8)>>>(W1);
    k_twm<<<dim3(E / 32, HE / 32), dim3(32, 8)>>>(Wm);
    k_x<<<BSZ / 8, 256>>>(x);
    k_y<<<BSZ, 256, SMEM_Y>>>(y, gamma);
    k_mma<0><<<dim3(E / 128, BSZ / 128, H), 256, SMEM_MMA>>>(x, nullptr, nullptr);
    k_mma<1><<<dim3(E / 128, BSZ / 128, 1), 256, SMEM_MMA>>>(x, bm, out);
}